// round 1
// baseline (speedup 1.0000x reference)
#include <cuda_runtime.h>
#include <cuda_bf16.h>
#include <math.h>

// ---------------------------------------------------------------------------
// Problem constants
// ---------------------------------------------------------------------------
#define NQ      6000      // fluid particles (queries)
#define NBOX    3000      // box particles
#define KMAX    80
#define CAP     256       // candidate capacity (overflow beyond KMAX essentially impossible)
#define KS      4
#define NCELL   64
#define RADIUS  0.1125f

// ---------------------------------------------------------------------------
// Device scratch (static allocation; no cudaMalloc allowed)
// ---------------------------------------------------------------------------
__device__ __align__(16) float g_S[(size_t)NQ * 64 * 96];     // 147.5 MB scatter scratch
__device__ __align__(16) float g_x96[NQ * 96];
__device__ __align__(16) float g_ya[NQ * 64];
__device__ __align__(16) float g_yb[NQ * 64];
__device__ __align__(16) float g_part[3 * NQ * 64];
__device__ __align__(16) float g_ff[NQ * 4];

__device__ int   g_fcnt[NQ];
__device__ int   g_fidx[NQ * KMAX];
__device__ int   g_fcell[NQ * KMAX];
__device__ __align__(16) float g_fcoef[(size_t)NQ * KMAX * 8];

__device__ int   g_ocnt[NQ];
__device__ int   g_oidx[NQ * KMAX];
__device__ int   g_ocell[NQ * KMAX];
__device__ __align__(16) float g_ocoef[(size_t)NQ * KMAX * 8];

// ---------------------------------------------------------------------------
// Helpers
// ---------------------------------------------------------------------------
__device__ __forceinline__ float2 ffma2(float2 a, float2 b, float2 c) {
    float2 d;
    asm("{\n\t"
        ".reg .b64 ra, rb, rc;\n\t"
        "mov.b64 ra, {%2, %3};\n\t"
        "mov.b64 rb, {%4, %5};\n\t"
        "mov.b64 rc, {%6, %7};\n\t"
        "fma.rn.f32x2 rc, ra, rb, rc;\n\t"
        "mov.b64 {%0, %1}, rc;\n\t"
        "}"
        : "=f"(d.x), "=f"(d.y)
        : "f"(a.x), "f"(a.y), "f"(b.x), "f"(b.y), "f"(c.x), "f"(c.y));
    return d;
}

__device__ __forceinline__ float fsign(float x) {
    return (x > 0.f) ? 1.f : ((x < 0.f) ? -1.f : 0.f);
}

// ---------------------------------------------------------------------------
// ff = [1, vel]
// ---------------------------------------------------------------------------
__global__ void build_ff_kernel(const float* __restrict__ vel) {
    int i = blockIdx.x * blockDim.x + threadIdx.x;
    if (i >= NQ) return;
    g_ff[i * 4 + 0] = 1.0f;
    g_ff[i * 4 + 1] = vel[i * 3 + 0];
    g_ff[i * 4 + 2] = vel[i * 3 + 1];
    g_ff[i * 4 + 3] = vel[i * 3 + 2];
}

// ---------------------------------------------------------------------------
// Neighbor search + window + ball->cube + trilinear coefs.
// One block per query.
// ---------------------------------------------------------------------------
__global__ void nbr_kernel(const float* __restrict__ pin, int nin,
                           const float* __restrict__ pout, int selfExcl,
                           int* __restrict__ cnt_out, int* __restrict__ idx_out,
                           int* __restrict__ cell_out, float* __restrict__ coef_out) {
    int i = blockIdx.x;
    __shared__ float sd2[CAP];
    __shared__ int   sj[CAP];
    __shared__ int   ssel[KMAX];
    __shared__ int   scnt, skeep;
    int tid = threadIdx.x;
    if (tid == 0) { scnt = 0; skeep = 0; }
    __syncthreads();

    float qx = pout[3 * i + 0], qy = pout[3 * i + 1], qz = pout[3 * i + 2];
    const float R2 = RADIUS * RADIUS;

    for (int j = tid; j < nin; j += blockDim.x) {
        if (selfExcl && j == i) continue;
        float dx = pin[3 * j + 0] - qx;
        float dy = pin[3 * j + 1] - qy;
        float dz = pin[3 * j + 2] - qz;
        float d2 = dx * dx + dy * dy + dz * dz;
        if (d2 <= R2) {
            int p = atomicAdd(&scnt, 1);
            if (p < CAP) { sd2[p] = d2; sj[p] = j; }
        }
    }
    __syncthreads();

    int cnt = min(scnt, CAP);
    int kcnt;
    if (cnt <= KMAX) {
        kcnt = cnt;
        for (int e = tid; e < cnt; e += blockDim.x) ssel[e] = sj[e];
    } else {
        kcnt = KMAX;
        // keep KMAX closest (tie-break by lower index, matching top_k)
        for (int e = tid; e < cnt; e += blockDim.x) {
            float m2 = sd2[e]; int mj = sj[e]; int rank = 0;
            for (int q = 0; q < cnt; q++) {
                float o2 = sd2[q];
                rank += (o2 < m2) || (o2 == m2 && sj[q] < mj);
            }
            if (rank < KMAX) { int p = atomicAdd(&skeep, 1); ssel[p] = mj; }
        }
    }
    __syncthreads();
    if (tid == 0) cnt_out[i] = kcnt;

    const float EPS = 1e-12f;
    const float FP  = (float)(4.0 / 3.14159265358979323846);

    for (int k = tid; k < kcnt; k += blockDim.x) {
        int j = ssel[k];
        float rx = (pin[3 * j + 0] - qx) / RADIUS;
        float ry = (pin[3 * j + 1] - qy) / RADIUS;
        float rz = (pin[3 * j + 2] - qz) / RADIUS;

        float sq = rx * rx + ry * ry + rz * rz;
        float p1m = 1.0f - sq;
        float win = p1m * p1m * p1m;
        win = fminf(fmaxf(win, 0.f), 1.f);

        // ball -> cylinder (volume preserving)
        float nrm  = sqrtf(sq);
        float rxy2 = rx * rx + ry * ry;
        bool  polar = (1.25f * rz * rz) > rxy2;
        float s_pol = sqrtf(3.0f * nrm / (nrm + fabsf(rz) + EPS));
        float s_eq  = nrm / sqrtf(rxy2 + EPS);
        float xc = polar ? s_pol * rx : s_eq * rx;
        float yc = polar ? s_pol * ry : s_eq * ry;
        float zc = polar ? fsign(rz) * nrm : 1.5f * rz * s_eq;
        if (sq < 1e-12f) { xc = 0.f; yc = 0.f; zc = 0.f; }

        // cylinder -> cube
        float rxy = sqrtf(xc * xc + yc * yc);
        float sx = (fabsf(xc) < EPS) ? EPS : xc;
        float sy = (fabsf(yc) < EPS) ? EPS : yc;
        float u1 = fsign(xc) * rxy;
        float v1 = u1 * FP * atanf(yc / sx);
        float v2 = fsign(yc) * rxy;
        float u2 = v2 * FP * atanf(xc / sy);
        float u, v;
        if (fabsf(xc) >= fabsf(yc)) { u = u1; v = v1; } else { u = u2; v = v2; }
        if (rxy < EPS) { u = 0.f; v = 0.f; }

        // trilinear grid
        float gx = fminf(fmaxf((u  + 1.0f) * 0.5f * (float)(KS - 1), 0.f), (float)(KS - 1));
        float gy = fminf(fmaxf((v  + 1.0f) * 0.5f * (float)(KS - 1), 0.f), (float)(KS - 1));
        float gz = fminf(fmaxf((zc + 1.0f) * 0.5f * (float)(KS - 1), 0.f), (float)(KS - 1));
        int ix = min((int)floorf(gx), KS - 2);
        int iy = min((int)floorf(gy), KS - 2);
        int iz = min((int)floorf(gz), KS - 2);
        float tx = gx - (float)ix, ty = gy - (float)iy, tz = gz - (float)iz;

        int slot = i * KMAX + k;
        idx_out[slot]  = j;
        cell_out[slot] = (iz * KS + iy) * KS + ix;

        float wx[2] = {1.f - tx, tx};
        float wy[2] = {1.f - ty, ty};
        float wz[2] = {1.f - tz, tz};
        float* cf = coef_out + (size_t)slot * 8;
        #pragma unroll
        for (int dx = 0; dx < 2; dx++)
            #pragma unroll
            for (int dy = 0; dy < 2; dy++)
                #pragma unroll
                for (int dz = 0; dz < 2; dz++)
                    cf[dx * 4 + dy * 2 + dz] = wx[dx] * wy[dy] * wz[dz] * win;
    }
}

// ---------------------------------------------------------------------------
// Scatter: S[i, cell, f] = sum_k coef[k,c] * feats[idx[k], f]
// One block per query; thread f owns feature column f (no races).
// ---------------------------------------------------------------------------
__global__ void scatter_kernel(const int* __restrict__ cnt, const int* __restrict__ nidx,
                               const int* __restrict__ ncell, const float* __restrict__ ncoef,
                               const float* __restrict__ feats, int F, int doRelu,
                               float* __restrict__ Sout) {
    int i = blockIdx.x;
    __shared__ float shS[64 * 96];
    __shared__ float shC[KMAX * 8];
    __shared__ int   shI[KMAX];
    __shared__ int   shCe[KMAX];
    int tid = threadIdx.x;
    int nF = 64 * F;

    for (int q = tid; q < nF; q += blockDim.x) shS[q] = 0.f;
    int c = cnt[i];
    for (int q = tid; q < c; q += blockDim.x) {
        shI[q]  = nidx[i * KMAX + q];
        shCe[q] = ncell[i * KMAX + q];
    }
    for (int q = tid; q < c * 8; q += blockDim.x)
        shC[q] = ncoef[(size_t)i * KMAX * 8 + q];
    __syncthreads();

    if (tid < F) {
        int f = tid;
        const int OFF[8] = {0, 16, 4, 20, 1, 17, 5, 21};  // dx + 4*dy + 16*dz for c = dx*4+dy*2+dz
        for (int k = 0; k < c; k++) {
            int j = shI[k];
            float vv = feats[(size_t)j * F + f];
            if (doRelu) vv = fmaxf(vv, 0.f);
            int base = shCe[k] * F + f;
            #pragma unroll
            for (int cc = 0; cc < 8; cc++)
                shS[base + OFF[cc] * F] += shC[k * 8 + cc] * vv;
        }
    }
    __syncthreads();

    float* dst = Sout + (size_t)i * nF;
    for (int q = tid; q < nF; q += blockDim.x) dst[q] = shS[q];
}

// ---------------------------------------------------------------------------
// GEMM, N = 64, fp32 with f32x2 packed FMA. grid = (ceil(M/64), nsplit).
// Split s handles k in [s*klen, (s+1)*klen) and writes partial to out + s*M*64.
// ---------------------------------------------------------------------------
__global__ void gemm64_k(const float* __restrict__ A, int lda, int M, int klen,
                         const float* __restrict__ W, float* __restrict__ outbase,
                         int reluA) {
    int bm = blockIdx.x * 64;
    int ks0 = blockIdx.y * klen;
    float* out = outbase + (size_t)blockIdx.y * M * 64;

    __shared__ float As[16][64];
    __shared__ float Bs[16][64];
    int tid = threadIdx.x;
    int ty = tid >> 4, tx = tid & 15;

    float2 acc[4][2];
    #pragma unroll
    for (int j = 0; j < 4; j++) { acc[j][0] = make_float2(0.f, 0.f); acc[j][1] = make_float2(0.f, 0.f); }

    int am = tid >> 2;          // 0..63
    int ak = (tid & 3) * 4;     // 0,4,8,12
    int bk = tid >> 4;          // 0..15
    int bn = (tid & 15) * 4;
    int arow = bm + am;

    for (int kt = ks0; kt < ks0 + klen; kt += 16) {
        float4 av = make_float4(0.f, 0.f, 0.f, 0.f);
        if (arow < M) {
            av = *(const float4*)(A + (size_t)arow * lda + kt + ak);
            if (reluA) {
                av.x = fmaxf(av.x, 0.f); av.y = fmaxf(av.y, 0.f);
                av.z = fmaxf(av.z, 0.f); av.w = fmaxf(av.w, 0.f);
            }
        }
        As[ak + 0][am] = av.x; As[ak + 1][am] = av.y;
        As[ak + 2][am] = av.z; As[ak + 3][am] = av.w;
        *(float4*)&Bs[bk][bn] = *(const float4*)(W + (size_t)(kt + bk) * 64 + bn);
        __syncthreads();

        #pragma unroll
        for (int kk = 0; kk < 16; kk++) {
            float4 a = *(const float4*)&As[kk][ty * 4];
            float4 b = *(const float4*)&Bs[kk][tx * 4];
            float2 a01 = make_float2(a.x, a.y);
            float2 a23 = make_float2(a.z, a.w);
            acc[0][0] = ffma2(a01, make_float2(b.x, b.x), acc[0][0]);
            acc[0][1] = ffma2(a23, make_float2(b.x, b.x), acc[0][1]);
            acc[1][0] = ffma2(a01, make_float2(b.y, b.y), acc[1][0]);
            acc[1][1] = ffma2(a23, make_float2(b.y, b.y), acc[1][1]);
            acc[2][0] = ffma2(a01, make_float2(b.z, b.z), acc[2][0]);
            acc[2][1] = ffma2(a23, make_float2(b.z, b.z), acc[2][1]);
            acc[3][0] = ffma2(a01, make_float2(b.w, b.w), acc[3][0]);
            acc[3][1] = ffma2(a23, make_float2(b.w, b.w), acc[3][1]);
        }
        __syncthreads();
    }

    int r0 = bm + ty * 4;
    #pragma unroll
    for (int j = 0; j < 4; j++) {
        int col = tx * 4 + j;
        if (r0 + 0 < M) out[(size_t)(r0 + 0) * 64 + col] = acc[j][0].x;
        if (r0 + 1 < M) out[(size_t)(r0 + 1) * 64 + col] = acc[j][0].y;
        if (r0 + 2 < M) out[(size_t)(r0 + 2) * 64 + col] = acc[j][1].x;
        if (r0 + 3 < M) out[(size_t)(r0 + 3) * 64 + col] = acc[j][1].y;
    }
}

// ---------------------------------------------------------------------------
// combine: out = p0 + p1 (+ p2) + b1 + b2 (+ res)
// ---------------------------------------------------------------------------
__global__ void combine_kernel(const float* __restrict__ p0, const float* __restrict__ p1,
                               const float* __restrict__ p2,
                               const float* __restrict__ b1, const float* __restrict__ b2,
                               const float* __restrict__ res, float* __restrict__ out, int M) {
    int idx = blockIdx.x * blockDim.x + threadIdx.x;
    if (idx >= M * 64) return;
    int c = idx & 63;
    float v = p0[idx] + p1[idx] + b1[c] + b2[c];
    if (p2)  v += p2[idx];
    if (res) v += res[idx];
    out[idx] = v;
}

// ---------------------------------------------------------------------------
// Small-O GEMM: one warp per output row. out = (prev? + A@W + bias) * scale
// ---------------------------------------------------------------------------
template <int O>
__global__ void gemm_small(const float* __restrict__ A, int lda, int M, int K, int reluA,
                           const float* __restrict__ W, const float* __restrict__ bias,
                           float* __restrict__ out, int ldo, int ooff,
                           int accumulate, float scale) {
    int warp = (blockIdx.x * blockDim.x + threadIdx.x) >> 5;
    int lane = threadIdx.x & 31;
    if (warp >= M) return;
    const float* Ar = A + (size_t)warp * lda;

    float acc[O];
    #pragma unroll
    for (int o = 0; o < O; o++) acc[o] = 0.f;

    for (int k = lane; k < K; k += 32) {
        float a = Ar[k];
        if (reluA) a = fmaxf(a, 0.f);
        const float* wr = W + (size_t)k * O;
        #pragma unroll
        for (int o = 0; o < O; o++) acc[o] += a * wr[o];
    }

    float myv = 0.f;
    #pragma unroll
    for (int o = 0; o < O; o++) {
        float v = acc[o];
        v += __shfl_xor_sync(0xffffffffu, v, 16);
        v += __shfl_xor_sync(0xffffffffu, v, 8);
        v += __shfl_xor_sync(0xffffffffu, v, 4);
        v += __shfl_xor_sync(0xffffffffu, v, 2);
        v += __shfl_xor_sync(0xffffffffu, v, 1);
        if (lane == o) myv = v;
    }
    if (lane < O) {
        float r = myv + (bias ? bias[lane] : 0.f);
        float* po = out + (size_t)warp * ldo + ooff + lane;
        if (accumulate) r += *po;
        *po = r * scale;
    }
}

// ---------------------------------------------------------------------------
// Host launch
// ---------------------------------------------------------------------------
template <typename T>
static T* symaddr(const void* sym) {
    void* p = nullptr;
    cudaGetSymbolAddress(&p, sym);
    return (T*)p;
}

extern "C" void kernel_launch(void* const* d_in, const int* in_sizes, int n_in,
                              void* d_out, int out_size) {
    const float* pos       = (const float*)d_in[0];
    const float* vel       = (const float*)d_in[1];
    const float* box       = (const float*)d_in[2];
    const float* box_feats = (const float*)d_in[3];
    const float* cf_w = (const float*)d_in[4];
    const float* cf_b = (const float*)d_in[5];
    const float* co_w = (const float*)d_in[6];
    const float* co_b = (const float*)d_in[7];
    const float* d0_w = (const float*)d_in[8];
    const float* d0_b = (const float*)d_in[9];
    const float* c1_w = (const float*)d_in[10];
    const float* c1_b = (const float*)d_in[11];
    const float* d1_w = (const float*)d_in[12];
    const float* d1_b = (const float*)d_in[13];
    const float* c2_w = (const float*)d_in[14];
    const float* c2_b = (const float*)d_in[15];
    const float* d2_w = (const float*)d_in[16];
    const float* d2_b = (const float*)d_in[17];
    const float* c3_w = (const float*)d_in[18];
    const float* c3_b = (const float*)d_in[19];
    const float* d3_w = (const float*)d_in[20];
    const float* d3_b = (const float*)d_in[21];
    float* out = (float*)d_out;

    float* S    = symaddr<float>(g_S);
    float* x96  = symaddr<float>(g_x96);
    float* ya   = symaddr<float>(g_ya);
    float* yb   = symaddr<float>(g_yb);
    float* part = symaddr<float>(g_part);
    float* ff   = symaddr<float>(g_ff);
    int*   fcnt  = symaddr<int>(g_fcnt);
    int*   fidx  = symaddr<int>(g_fidx);
    int*   fcell = symaddr<int>(g_fcell);
    float* fcoef = symaddr<float>(g_fcoef);
    int*   ocnt  = symaddr<int>(g_ocnt);
    int*   oidx  = symaddr<int>(g_oidx);
    int*   ocell = symaddr<int>(g_ocell);
    float* ocoef = symaddr<float>(g_ocoef);

    const int M = NQ;
    float* part0 = part;
    float* part1 = part + (size_t)M * 64;
    float* part2 = part + 2 * (size_t)M * 64;

    // 0) ff = [1, vel]
    build_ff_kernel<<<(NQ + 255) / 256, 256>>>(vel);

    // 1) neighbor lists
    nbr_kernel<<<NQ, 256>>>(pos, NQ, pos, 1, fcnt, fidx, fcell, fcoef);
    nbr_kernel<<<NQ, 256>>>(box, NBOX, pos, 0, ocnt, oidx, ocell, ocoef);

    // 2) first block: x96 = [a_co | a_cf | a_d0]
    scatter_kernel<<<NQ, 128>>>(fcnt, fidx, fcell, fcoef, ff, 4, 0, S);
    gemm_small<32><<<(M * 32 + 255) / 256, 256>>>(S, 256, M, 256, 0, cf_w, cf_b, x96, 96, 32, 0, 1.f);
    scatter_kernel<<<NQ, 128>>>(ocnt, oidx, ocell, ocoef, box_feats, 3, 0, S);
    gemm_small<32><<<(M * 32 + 255) / 256, 256>>>(S, 192, M, 192, 0, co_w, co_b, x96, 96, 0, 0, 1.f);
    gemm_small<32><<<(M * 32 + 255) / 256, 256>>>(ff, 4, M, 4, 0, d0_w, d0_b, x96, 96, 64, 0, 1.f);

    dim3 g2((M + 63) / 64, 2);
    dim3 g1((M + 63) / 64, 1);

    // 3) layer 1: ya = cconv(relu(x96), c1) + c1_b + relu(x96)@d1_w + d1_b
    scatter_kernel<<<NQ, 128>>>(fcnt, fidx, fcell, fcoef, x96, 96, 1, S);
    gemm64_k<<<g2, 256>>>(S, 6144, M, 3072, c1_w, part, 0);
    gemm64_k<<<g1, 256>>>(x96, 96, M, 96, d1_w, part2, 1);
    combine_kernel<<<(M * 64 + 255) / 256, 256>>>(part0, part1, part2, c1_b, d1_b, nullptr, ya, M);

    // 4) layer 2: yb = cconv(relu(ya), c2) + c2_b + relu(ya)@d2_w + d2_b + ya
    scatter_kernel<<<NQ, 128>>>(fcnt, fidx, fcell, fcoef, ya, 64, 1, S);
    gemm64_k<<<g2, 256>>>(S, 4096, M, 2048, c2_w, part, 0);
    gemm64_k<<<g1, 256>>>(ya, 64, M, 64, d2_w, part2, 1);
    combine_kernel<<<(M * 64 + 255) / 256, 256>>>(part0, part1, part2, c2_b, d2_b, ya, yb, M);

    // 5) layer 3: out = (cconv(relu(yb), c3) + c3_b + relu(yb)@d3_w + d3_b) / 128
    scatter_kernel<<<NQ, 128>>>(fcnt, fidx, fcell, fcoef, yb, 64, 1, S);
    gemm_small<3><<<(M * 32 + 255) / 256, 256>>>(S, 4096, M, 4096, 0, c3_w, c3_b, out, 3, 0, 0, 1.f);
    gemm_small<3><<<(M * 32 + 255) / 256, 256>>>(yb, 64, M, 64, 1, d3_w, d3_b, out, 3, 0, 1, 1.0f / 128.0f);
}

// round 3
// speedup vs baseline: 1.2666x; 1.2666x over previous
#include <cuda_runtime.h>
#include <cuda_bf16.h>
#include <math.h>

// ---------------------------------------------------------------------------
// Problem constants
// ---------------------------------------------------------------------------
#define NQ      6000      // fluid particles (queries)
#define NBOX    3000      // box particles
#define KMAX    80
#define CAP     256       // accepted-neighbor capacity per query
#define KS      4
#define NCELL   64
#define RADIUS  0.1125f

#define GDIM    8         // hash grid 8^3, cell width 0.125 > RADIUS
#define NCELLS  (GDIM*GDIM*GDIM)

// ---------------------------------------------------------------------------
// Device scratch (static allocation; no cudaMalloc allowed)
// ---------------------------------------------------------------------------
__device__ __align__(16) float g_S[(size_t)NQ * 64 * 96];     // 147.5 MB scatter scratch
__device__ __align__(16) float g_x96[NQ * 96];
__device__ __align__(16) float g_ya[NQ * 64];
__device__ __align__(16) float g_yb[NQ * 64];
__device__ __align__(16) float g_part[3 * NQ * 64];
__device__ __align__(16) float g_ff[NQ * 4];

__device__ int   g_fcnt[NQ];
__device__ int   g_fidx[NQ * KMAX];
__device__ int   g_fcell[NQ * KMAX];
__device__ __align__(16) float g_fcoef[(size_t)NQ * KMAX * 8];

__device__ int   g_ocnt[NQ];
__device__ int   g_oidx[NQ * KMAX];
__device__ int   g_ocell[NQ * KMAX];
__device__ __align__(16) float g_ocoef[(size_t)NQ * KMAX * 8];

// hash grids (0 = fluid/pos, 1 = box)
__device__ int g_gcnt[2][NCELLS];
__device__ int g_gstart[2][NCELLS + 1];
__device__ int g_gcur[2][NCELLS];
__device__ int g_glistF[NQ];
__device__ int g_glistB[NBOX];

// ---------------------------------------------------------------------------
// Helpers
// ---------------------------------------------------------------------------
__device__ __forceinline__ float2 ffma2(float2 a, float2 b, float2 c) {
    float2 d;
    asm("{\n\t"
        ".reg .b64 ra, rb, rc;\n\t"
        "mov.b64 ra, {%2, %3};\n\t"
        "mov.b64 rb, {%4, %5};\n\t"
        "mov.b64 rc, {%6, %7};\n\t"
        "fma.rn.f32x2 rc, ra, rb, rc;\n\t"
        "mov.b64 {%0, %1}, rc;\n\t"
        "}"
        : "=f"(d.x), "=f"(d.y)
        : "f"(a.x), "f"(a.y), "f"(b.x), "f"(b.y), "f"(c.x), "f"(c.y));
    return d;
}

__device__ __forceinline__ float fsign(float x) {
    return (x > 0.f) ? 1.f : ((x < 0.f) ? -1.f : 0.f);
}

__device__ __forceinline__ int cell_coord(float x) {
    int c = (int)(x * (float)GDIM);
    return min(max(c, 0), GDIM - 1);
}

// ---------------------------------------------------------------------------
// ff = [1, vel]
// ---------------------------------------------------------------------------
__global__ void build_ff_kernel(const float* __restrict__ vel) {
    int i = blockIdx.x * blockDim.x + threadIdx.x;
    if (i >= NQ) return;
    g_ff[i * 4 + 0] = 1.0f;
    g_ff[i * 4 + 1] = vel[i * 3 + 0];
    g_ff[i * 4 + 2] = vel[i * 3 + 1];
    g_ff[i * 4 + 3] = vel[i * 3 + 2];
}

// ---------------------------------------------------------------------------
// Hash grid build: zero -> hist -> scan -> fill
// ---------------------------------------------------------------------------
__global__ void grid_zero(int* __restrict__ cnt) {
    cnt[threadIdx.x] = 0;
}

__global__ void grid_hist(const float* __restrict__ p, int n, int* __restrict__ cnt) {
    int i = blockIdx.x * blockDim.x + threadIdx.x;
    if (i >= n) return;
    int cx = cell_coord(p[3 * i + 0]);
    int cy = cell_coord(p[3 * i + 1]);
    int cz = cell_coord(p[3 * i + 2]);
    atomicAdd(&cnt[(cz * GDIM + cy) * GDIM + cx], 1);
}

__global__ void grid_scan(const int* __restrict__ cnt, int* __restrict__ start,
                          int* __restrict__ cur) {
    __shared__ int s[NCELLS];
    int t = threadIdx.x;
    int v = cnt[t];
    s[t] = v;
    __syncthreads();
    for (int off = 1; off < NCELLS; off <<= 1) {
        int x = (t >= off) ? s[t - off] : 0;
        __syncthreads();
        s[t] += x;
        __syncthreads();
    }
    start[t + 1] = s[t];
    cur[t] = s[t] - v;   // exclusive prefix
    if (t == 0) start[0] = 0;
}

__global__ void grid_fill(const float* __restrict__ p, int n, int* __restrict__ cur,
                          int* __restrict__ list) {
    int i = blockIdx.x * blockDim.x + threadIdx.x;
    if (i >= n) return;
    int cx = cell_coord(p[3 * i + 0]);
    int cy = cell_coord(p[3 * i + 1]);
    int cz = cell_coord(p[3 * i + 2]);
    int slot = atomicAdd(&cur[(cz * GDIM + cy) * GDIM + cx], 1);
    list[slot] = i;
}

// ---------------------------------------------------------------------------
// Grid-accelerated neighbor search + window + ball->cube + trilinear coefs.
// One block (64 threads) per query.
// ---------------------------------------------------------------------------
__global__ void nbr_grid_kernel(const float* __restrict__ pin,
                                const float* __restrict__ pout, int selfExcl,
                                const int* __restrict__ gstart, const int* __restrict__ glist,
                                int* __restrict__ cnt_out, int* __restrict__ idx_out,
                                int* __restrict__ cell_out, float* __restrict__ coef_out) {
    int i = blockIdx.x;
    __shared__ float sd2[CAP];
    __shared__ int   sj[CAP];
    __shared__ int   ssel[KMAX];
    __shared__ int   scnt, skeep;
    int tid = threadIdx.x;
    if (tid == 0) { scnt = 0; skeep = 0; }
    __syncthreads();

    float qx = pout[3 * i + 0], qy = pout[3 * i + 1], qz = pout[3 * i + 2];
    const float R2 = RADIUS * RADIUS;

    int cx = cell_coord(qx), cy = cell_coord(qy), cz = cell_coord(qz);
    int x0 = max(cx - 1, 0), x1 = min(cx + 1, GDIM - 1);
    int y0 = max(cy - 1, 0), y1 = min(cy + 1, GDIM - 1);
    int z0 = max(cz - 1, 0), z1 = min(cz + 1, GDIM - 1);

    for (int z = z0; z <= z1; z++) {
        for (int y = y0; y <= y1; y++) {
            int cbase = (z * GDIM + y) * GDIM;
            int b = gstart[cbase + x0];
            int e = gstart[cbase + x1 + 1];
            for (int t = b + tid; t < e; t += blockDim.x) {
                int j = glist[t];
                if (selfExcl && j == i) continue;
                float dx = pin[3 * j + 0] - qx;
                float dy = pin[3 * j + 1] - qy;
                float dz = pin[3 * j + 2] - qz;
                float d2 = dx * dx + dy * dy + dz * dz;
                if (d2 <= R2) {
                    int p = atomicAdd(&scnt, 1);
                    if (p < CAP) { sd2[p] = d2; sj[p] = j; }
                }
            }
        }
    }
    __syncthreads();

    int cnt = min(scnt, CAP);
    int kcnt;
    if (cnt <= KMAX) {
        kcnt = cnt;
        for (int e = tid; e < cnt; e += blockDim.x) ssel[e] = sj[e];
    } else {
        kcnt = KMAX;
        // keep KMAX closest (tie-break by lower index, matching top_k)
        for (int e = tid; e < cnt; e += blockDim.x) {
            float m2 = sd2[e]; int mj = sj[e]; int rank = 0;
            for (int q = 0; q < cnt; q++) {
                float o2 = sd2[q];
                rank += (o2 < m2) || (o2 == m2 && sj[q] < mj);
            }
            if (rank < KMAX) { int p = atomicAdd(&skeep, 1); ssel[p] = mj; }
        }
    }
    __syncthreads();
    if (tid == 0) cnt_out[i] = kcnt;

    const float EPS = 1e-12f;
    const float FP  = (float)(4.0 / 3.14159265358979323846);

    for (int k = tid; k < kcnt; k += blockDim.x) {
        int j = ssel[k];
        float rx = (pin[3 * j + 0] - qx) / RADIUS;
        float ry = (pin[3 * j + 1] - qy) / RADIUS;
        float rz = (pin[3 * j + 2] - qz) / RADIUS;

        float sq = rx * rx + ry * ry + rz * rz;
        float p1m = 1.0f - sq;
        float win = p1m * p1m * p1m;
        win = fminf(fmaxf(win, 0.f), 1.f);

        // ball -> cylinder (volume preserving)
        float nrm  = sqrtf(sq);
        float rxy2 = rx * rx + ry * ry;
        bool  polar = (1.25f * rz * rz) > rxy2;
        float s_pol = sqrtf(3.0f * nrm / (nrm + fabsf(rz) + EPS));
        float s_eq  = nrm / sqrtf(rxy2 + EPS);
        float xc = polar ? s_pol * rx : s_eq * rx;
        float yc = polar ? s_pol * ry : s_eq * ry;
        float zc = polar ? fsign(rz) * nrm : 1.5f * rz * s_eq;
        if (sq < 1e-12f) { xc = 0.f; yc = 0.f; zc = 0.f; }

        // cylinder -> cube
        float rxy = sqrtf(xc * xc + yc * yc);
        float sx = (fabsf(xc) < EPS) ? EPS : xc;
        float sy = (fabsf(yc) < EPS) ? EPS : yc;
        float u1 = fsign(xc) * rxy;
        float v1 = u1 * FP * atanf(yc / sx);
        float v2 = fsign(yc) * rxy;
        float u2 = v2 * FP * atanf(xc / sy);
        float u, v;
        if (fabsf(xc) >= fabsf(yc)) { u = u1; v = v1; } else { u = u2; v = v2; }
        if (rxy < EPS) { u = 0.f; v = 0.f; }

        // trilinear grid
        float gx = fminf(fmaxf((u  + 1.0f) * 0.5f * (float)(KS - 1), 0.f), (float)(KS - 1));
        float gy = fminf(fmaxf((v  + 1.0f) * 0.5f * (float)(KS - 1), 0.f), (float)(KS - 1));
        float gz = fminf(fmaxf((zc + 1.0f) * 0.5f * (float)(KS - 1), 0.f), (float)(KS - 1));
        int ix = min((int)floorf(gx), KS - 2);
        int iy = min((int)floorf(gy), KS - 2);
        int iz = min((int)floorf(gz), KS - 2);
        float tx = gx - (float)ix, ty = gy - (float)iy, tz = gz - (float)iz;

        int slot = i * KMAX + k;
        idx_out[slot]  = j;
        cell_out[slot] = (iz * KS + iy) * KS + ix;

        float wx[2] = {1.f - tx, tx};
        float wy[2] = {1.f - ty, ty};
        float wz[2] = {1.f - tz, tz};
        float* cf = coef_out + (size_t)slot * 8;
        #pragma unroll
        for (int dx = 0; dx < 2; dx++)
            #pragma unroll
            for (int dy = 0; dy < 2; dy++)
                #pragma unroll
                for (int dz = 0; dz < 2; dz++)
                    cf[dx * 4 + dy * 2 + dz] = wx[dx] * wy[dy] * wz[dz] * win;
    }
}

// ---------------------------------------------------------------------------
// Scatter with k-split: SPLIT private copies of S in shared, threads = F*SPLIT,
// thread (f, s) accumulates its k-range into its own copy, then reduce+store.
// ---------------------------------------------------------------------------
template <int F, int SPLIT>
__global__ void scatter_split(const int* __restrict__ cnt, const int* __restrict__ nidx,
                              const int* __restrict__ ncell, const float* __restrict__ ncoef,
                              const float* __restrict__ feats, int doRelu,
                              float* __restrict__ Sout) {
    int i = blockIdx.x;
    extern __shared__ float shS[];            // SPLIT * 64 * F
    __shared__ float shC[KMAX * 8];
    __shared__ int   shI[KMAX];
    __shared__ int   shCe[KMAX];
    int tid = threadIdx.x;
    const int NT = F * SPLIT;
    const int nF = 64 * F;

    for (int q = tid; q < SPLIT * nF; q += NT) shS[q] = 0.f;
    int c = cnt[i];
    for (int q = tid; q < c; q += NT) {
        shI[q]  = nidx[i * KMAX + q];
        shCe[q] = ncell[i * KMAX + q];
    }
    for (int q = tid; q < c * 8; q += NT)
        shC[q] = ncoef[(size_t)i * KMAX * 8 + q];
    __syncthreads();

    {
        int f = tid % F;
        int s = tid / F;
        int k0 = (c * s) / SPLIT;
        int k1 = (c * (s + 1)) / SPLIT;
        float* my = shS + s * nF;
        const int OFF[8] = {0, 16, 4, 20, 1, 17, 5, 21};  // dz*16+dy*4+dx for c = dx*4+dy*2+dz
        for (int k = k0; k < k1; k++) {
            int j = shI[k];
            float vv = feats[(size_t)j * F + f];
            if (doRelu) vv = fmaxf(vv, 0.f);
            int base = shCe[k] * F + f;
            #pragma unroll
            for (int cc = 0; cc < 8; cc++)
                my[base + OFF[cc] * F] += shC[k * 8 + cc] * vv;
        }
    }
    __syncthreads();

    float* dst = Sout + (size_t)i * nF;
    for (int q = tid; q < nF; q += NT) {
        float v = shS[q];
        #pragma unroll
        for (int s = 1; s < SPLIT; s++) v += shS[s * nF + q];
        dst[q] = v;
    }
}

// ---------------------------------------------------------------------------
// GEMM, N = 64, fp32 with f32x2 packed FMA. grid = (ceil(M/64), nsplit).
// ---------------------------------------------------------------------------
__global__ void gemm64_k(const float* __restrict__ A, int lda, int M, int klen,
                         const float* __restrict__ W, float* __restrict__ outbase,
                         int reluA) {
    int bm = blockIdx.x * 64;
    int ks0 = blockIdx.y * klen;
    float* out = outbase + (size_t)blockIdx.y * M * 64;

    __shared__ float As[16][64];
    __shared__ float Bs[16][64];
    int tid = threadIdx.x;
    int ty = tid >> 4, tx = tid & 15;

    float2 acc[4][2];
    #pragma unroll
    for (int j = 0; j < 4; j++) { acc[j][0] = make_float2(0.f, 0.f); acc[j][1] = make_float2(0.f, 0.f); }

    int am = tid >> 2;          // 0..63
    int ak = (tid & 3) * 4;     // 0,4,8,12
    int bk = tid >> 4;          // 0..15
    int bn = (tid & 15) * 4;
    int arow = bm + am;

    for (int kt = ks0; kt < ks0 + klen; kt += 16) {
        float4 av = make_float4(0.f, 0.f, 0.f, 0.f);
        if (arow < M) {
            av = *(const float4*)(A + (size_t)arow * lda + kt + ak);
            if (reluA) {
                av.x = fmaxf(av.x, 0.f); av.y = fmaxf(av.y, 0.f);
                av.z = fmaxf(av.z, 0.f); av.w = fmaxf(av.w, 0.f);
            }
        }
        As[ak + 0][am] = av.x; As[ak + 1][am] = av.y;
        As[ak + 2][am] = av.z; As[ak + 3][am] = av.w;
        *(float4*)&Bs[bk][bn] = *(const float4*)(W + (size_t)(kt + bk) * 64 + bn);
        __syncthreads();

        #pragma unroll
        for (int kk = 0; kk < 16; kk++) {
            float4 a = *(const float4*)&As[kk][ty * 4];
            float4 b = *(const float4*)&Bs[kk][tx * 4];
            float2 a01 = make_float2(a.x, a.y);
            float2 a23 = make_float2(a.z, a.w);
            acc[0][0] = ffma2(a01, make_float2(b.x, b.x), acc[0][0]);
            acc[0][1] = ffma2(a23, make_float2(b.x, b.x), acc[0][1]);
            acc[1][0] = ffma2(a01, make_float2(b.y, b.y), acc[1][0]);
            acc[1][1] = ffma2(a23, make_float2(b.y, b.y), acc[1][1]);
            acc[2][0] = ffma2(a01, make_float2(b.z, b.z), acc[2][0]);
            acc[2][1] = ffma2(a23, make_float2(b.z, b.z), acc[2][1]);
            acc[3][0] = ffma2(a01, make_float2(b.w, b.w), acc[3][0]);
            acc[3][1] = ffma2(a23, make_float2(b.w, b.w), acc[3][1]);
        }
        __syncthreads();
    }

    int r0 = bm + ty * 4;
    #pragma unroll
    for (int j = 0; j < 4; j++) {
        int col = tx * 4 + j;
        if (r0 + 0 < M) out[(size_t)(r0 + 0) * 64 + col] = acc[j][0].x;
        if (r0 + 1 < M) out[(size_t)(r0 + 1) * 64 + col] = acc[j][0].y;
        if (r0 + 2 < M) out[(size_t)(r0 + 2) * 64 + col] = acc[j][1].x;
        if (r0 + 3 < M) out[(size_t)(r0 + 3) * 64 + col] = acc[j][1].y;
    }
}

// ---------------------------------------------------------------------------
// combine: out = p0 + p1 (+ p2) + b1 + b2 (+ res)
// ---------------------------------------------------------------------------
__global__ void combine_kernel(const float* __restrict__ p0, const float* __restrict__ p1,
                               const float* __restrict__ p2,
                               const float* __restrict__ b1, const float* __restrict__ b2,
                               const float* __restrict__ res, float* __restrict__ out, int M) {
    int idx = blockIdx.x * blockDim.x + threadIdx.x;
    if (idx >= M * 64) return;
    int c = idx & 63;
    float v = p0[idx] + p1[idx] + b1[c] + b2[c];
    if (p2)  v += p2[idx];
    if (res) v += res[idx];
    out[idx] = v;
}

// ---------------------------------------------------------------------------
// Small-O GEMM with W cached in shared: one warp per output row, 8 rows/block.
// out = (prev? + A@W + bias) * scale
// ---------------------------------------------------------------------------
template <int O>
__global__ void gemm_small(const float* __restrict__ A, int lda, int M, int K, int reluA,
                           const float* __restrict__ W, const float* __restrict__ bias,
                           float* __restrict__ out, int ldo, int ooff,
                           int accumulate, float scale) {
    extern __shared__ float sW[];   // K * O
    int tid = threadIdx.x;
    for (int q = tid; q < K * O; q += blockDim.x) sW[q] = W[q];
    __syncthreads();

    int warp = blockIdx.x * (blockDim.x >> 5) + (tid >> 5);
    int lane = tid & 31;
    if (warp >= M) return;
    const float* Ar = A + (size_t)warp * lda;

    float acc[O];
    #pragma unroll
    for (int o = 0; o < O; o++) acc[o] = 0.f;

    for (int k = lane; k < K; k += 32) {
        float a = Ar[k];
        if (reluA) a = fmaxf(a, 0.f);
        const float* wr = sW + k * O;
        #pragma unroll
        for (int o = 0; o < O; o++) acc[o] += a * wr[o];
    }

    float myv = 0.f;
    #pragma unroll
    for (int o = 0; o < O; o++) {
        float v = acc[o];
        v += __shfl_xor_sync(0xffffffffu, v, 16);
        v += __shfl_xor_sync(0xffffffffu, v, 8);
        v += __shfl_xor_sync(0xffffffffu, v, 4);
        v += __shfl_xor_sync(0xffffffffu, v, 2);
        v += __shfl_xor_sync(0xffffffffu, v, 1);
        if (lane == o) myv = v;
    }
    if (lane < O) {
        float r = myv + (bias ? bias[lane] : 0.f);
        float* po = out + (size_t)warp * ldo + ooff + lane;
        if (accumulate) r += *po;
        *po = r * scale;
    }
}

// ---------------------------------------------------------------------------
// Host launch
// ---------------------------------------------------------------------------
template <typename T>
static T* symaddr(const void* sym) {
    void* p = nullptr;
    cudaGetSymbolAddress(&p, sym);
    return (T*)p;
}

extern "C" void kernel_launch(void* const* d_in, const int* in_sizes, int n_in,
                              void* d_out, int out_size) {
    // Raise dynamic smem limits (host-side attribute, idempotent, not a stream op)
    cudaFuncSetAttribute(scatter_split<96, 2>, cudaFuncAttributeMaxDynamicSharedMemorySize, 60 * 1024);
    cudaFuncSetAttribute(scatter_split<64, 3>, cudaFuncAttributeMaxDynamicSharedMemorySize, 60 * 1024);
    cudaFuncSetAttribute(scatter_split<4, 32>, cudaFuncAttributeMaxDynamicSharedMemorySize, 60 * 1024);
    cudaFuncSetAttribute(scatter_split<3, 32>, cudaFuncAttributeMaxDynamicSharedMemorySize, 60 * 1024);
    cudaFuncSetAttribute(gemm_small<3>, cudaFuncAttributeMaxDynamicSharedMemorySize, 60 * 1024);
    cudaFuncSetAttribute(gemm_small<32>, cudaFuncAttributeMaxDynamicSharedMemorySize, 60 * 1024);

    const float* pos       = (const float*)d_in[0];
    const float* vel       = (const float*)d_in[1];
    const float* box       = (const float*)d_in[2];
    const float* box_feats = (const float*)d_in[3];
    const float* cf_w = (const float*)d_in[4];
    const float* cf_b = (const float*)d_in[5];
    const float* co_w = (const float*)d_in[6];
    const float* co_b = (const float*)d_in[7];
    const float* d0_w = (const float*)d_in[8];
    const float* d0_b = (const float*)d_in[9];
    const float* c1_w = (const float*)d_in[10];
    const float* c1_b = (const float*)d_in[11];
    const float* d1_w = (const float*)d_in[12];
    const float* d1_b = (const float*)d_in[13];
    const float* c2_w = (const float*)d_in[14];
    const float* c2_b = (const float*)d_in[15];
    const float* d2_w = (const float*)d_in[16];
    const float* d2_b = (const float*)d_in[17];
    const float* c3_w = (const float*)d_in[18];
    const float* c3_b = (const float*)d_in[19];
    const float* d3_w = (const float*)d_in[20];
    const float* d3_b = (const float*)d_in[21];
    float* out = (float*)d_out;

    float* S    = symaddr<float>(g_S);
    float* x96  = symaddr<float>(g_x96);
    float* ya   = symaddr<float>(g_ya);
    float* yb   = symaddr<float>(g_yb);
    float* part = symaddr<float>(g_part);
    float* ff   = symaddr<float>(g_ff);
    int*   fcnt  = symaddr<int>(g_fcnt);
    int*   fidx  = symaddr<int>(g_fidx);
    int*   fcell = symaddr<int>(g_fcell);
    float* fcoef = symaddr<float>(g_fcoef);
    int*   ocnt  = symaddr<int>(g_ocnt);
    int*   oidx  = symaddr<int>(g_oidx);
    int*   ocell = symaddr<int>(g_ocell);
    float* ocoef = symaddr<float>(g_ocoef);
    int*   gcnt   = symaddr<int>(g_gcnt);     // [2][NCELLS]
    int*   gstart = symaddr<int>(g_gstart);   // [2][NCELLS+1]
    int*   gcur   = symaddr<int>(g_gcur);     // [2][NCELLS]
    int*   glistF = symaddr<int>(g_glistF);
    int*   glistB = symaddr<int>(g_glistB);

    const int M = NQ;
    float* part0 = part;
    float* part1 = part + (size_t)M * 64;
    float* part2 = part + 2 * (size_t)M * 64;

    // 0) ff = [1, vel]
    build_ff_kernel<<<(NQ + 255) / 256, 256>>>(vel);

    // 1) build hash grids (fluid, box)
    grid_zero<<<1, NCELLS>>>(gcnt);
    grid_zero<<<1, NCELLS>>>(gcnt + NCELLS);
    grid_hist<<<(NQ + 255) / 256, 256>>>(pos, NQ, gcnt);
    grid_hist<<<(NBOX + 255) / 256, 256>>>(box, NBOX, gcnt + NCELLS);
    grid_scan<<<1, NCELLS>>>(gcnt, gstart, gcur);
    grid_scan<<<1, NCELLS>>>(gcnt + NCELLS, gstart + NCELLS + 1, gcur + NCELLS);
    grid_fill<<<(NQ + 255) / 256, 256>>>(pos, NQ, gcur, glistF);
    grid_fill<<<(NBOX + 255) / 256, 256>>>(box, NBOX, gcur + NCELLS, glistB);

    // 2) neighbor lists
    nbr_grid_kernel<<<NQ, 64>>>(pos, pos, 1, gstart, glistF, fcnt, fidx, fcell, fcoef);
    nbr_grid_kernel<<<NQ, 64>>>(box, pos, 0, gstart + NCELLS + 1, glistB, ocnt, oidx, ocell, ocoef);

    // 3) first block: x96 = [a_co | a_cf | a_d0]
    scatter_split<4, 32><<<NQ, 128, 32 * 64 * 4 * 4>>>(fcnt, fidx, fcell, fcoef, ff, 0, S);
    gemm_small<32><<<(M + 7) / 8, 256, 256 * 32 * 4>>>(S, 256, M, 256, 0, cf_w, cf_b, x96, 96, 32, 0, 1.f);
    scatter_split<3, 32><<<NQ, 96, 32 * 64 * 3 * 4>>>(ocnt, oidx, ocell, ocoef, box_feats, 0, S);
    gemm_small<32><<<(M + 7) / 8, 256, 192 * 32 * 4>>>(S, 192, M, 192, 0, co_w, co_b, x96, 96, 0, 0, 1.f);
    gemm_small<32><<<(M + 7) / 8, 256, 4 * 32 * 4>>>(ff, 4, M, 4, 0, d0_w, d0_b, x96, 96, 64, 0, 1.f);

    dim3 g2((M + 63) / 64, 2);
    dim3 g1((M + 63) / 64, 1);

    // 4) layer 1: ya = cconv(relu(x96), c1) + c1_b + relu(x96)@d1_w + d1_b
    scatter_split<96, 2><<<NQ, 192, 2 * 64 * 96 * 4>>>(fcnt, fidx, fcell, fcoef, x96, 1, S);
    gemm64_k<<<g2, 256>>>(S, 6144, M, 3072, c1_w, part, 0);
    gemm64_k<<<g1, 256>>>(x96, 96, M, 96, d1_w, part2, 1);
    combine_kernel<<<(M * 64 + 255) / 256, 256>>>(part0, part1, part2, c1_b, d1_b, nullptr, ya, M);

    // 5) layer 2: yb = cconv(relu(ya), c2) + c2_b + relu(ya)@d2_w + d2_b + ya
    scatter_split<64, 3><<<NQ, 192, 3 * 64 * 64 * 4>>>(fcnt, fidx, fcell, fcoef, ya, 1, S);
    gemm64_k<<<g2, 256>>>(S, 4096, M, 2048, c2_w, part, 0);
    gemm64_k<<<g1, 256>>>(ya, 64, M, 64, d2_w, part2, 1);
    combine_kernel<<<(M * 64 + 255) / 256, 256>>>(part0, part1, part2, c2_b, d2_b, ya, yb, M);

    // 6) layer 3: out = (cconv(relu(yb), c3) + c3_b + relu(yb)@d3_w + d3_b) / 128
    scatter_split<64, 3><<<NQ, 192, 3 * 64 * 64 * 4>>>(fcnt, fidx, fcell, fcoef, yb, 1, S);
    gemm_small<3><<<(M + 7) / 8, 256, 4096 * 3 * 4>>>(S, 4096, M, 4096, 0, c3_w, c3_b, out, 3, 0, 0, 1.f);
    gemm_small<3><<<(M + 7) / 8, 256, 64 * 3 * 4>>>(yb, 64, M, 64, 1, d3_w, d3_b, out, 3, 0, 1, 1.0f / 128.0f);
}